// round 6
// baseline (speedup 1.0000x reference)
#include <cuda_runtime.h>
#include <math.h>

#define TOPK     1024
#define DFEAT    32
#define HBINS    4096          // top-12-bit histogram
#define CAND_CAP 2048
#define EQ_CAP   1024
#define MAXB     256

__device__ unsigned g_keys[4000000];
__device__ unsigned g_hist[MAXB * HBINS];

// ---------------------------------------------------------------------------
// Kernel 1: 4 threads/point, 2x float4 each (MLP=2, coalesced nL=8).
// Score -> order-preserving key (coalesced store) + global REDG histogram.
// ---------------------------------------------------------------------------
__global__ void score_kernel(const float* __restrict__ x,
                             const float* __restrict__ w,
                             const float* __restrict__ b,
                             unsigned* __restrict__ keys,
                             unsigned* __restrict__ hist,
                             int npts, int L)
{
    const int t = blockIdx.x * blockDim.x + threadIdx.x;
    const int point = t >> 2;
    const int q = t & 3;
    if (point >= npts) return;

    const float4* __restrict__ row = (const float4*)(x + (size_t)point * DFEAT);
    const float4 x0 = __ldg(row + q);
    const float4 x1 = __ldg(row + q + 4);
    const float4 w0 = __ldg((const float4*)w + q);
    const float4 w1 = __ldg((const float4*)w + q + 4);

    float s = x0.x * w0.x + x0.y * w0.y + x0.z * w0.z + x0.w * w0.w
            + x1.x * w1.x + x1.y * w1.y + x1.z * w1.z + x1.w * w1.w;
    s += __shfl_xor_sync(0xffffffffu, s, 1);
    s += __shfl_xor_sync(0xffffffffu, s, 2);

    if (q == 0) {
        s += __ldg(b);
        unsigned u = __float_as_uint(s);
        u = (u & 0x80000000u) ? ~u : (u | 0x80000000u);   // monotone transform
        keys[point] = u;
        const int seg = point / L;
        atomicAdd(&hist[seg * HBINS + (u >> 20)], 1u);    // REDG, L2-side
    }
}

// warp-aggregated compaction offset; ALL lanes of the warp must call.
__device__ __forceinline__ int warp_offset(bool pred, int* counter, int lane,
                                           unsigned& mask_out)
{
    const unsigned m = __ballot_sync(0xffffffffu, pred);
    mask_out = m;
    int pos = 0;
    if (m) {
        const int leader = __ffs(m) - 1;
        if (lane == leader) pos = atomicAdd(counter, __popc(m));
        pos = __shfl_sync(0xffffffffu, pos, leader);
    }
    return pos + __popc(m & ((1u << lane) - 1u));
}

// ---------------------------------------------------------------------------
// Kernel 2: one block per segment. Histogram arrives precomputed in gmem.
// ---------------------------------------------------------------------------
__global__ __launch_bounds__(1024, 1)
void select_reduce_kernel(const float* __restrict__ x,
                          const unsigned* __restrict__ keys,
                          const unsigned* __restrict__ hist,
                          float* __restrict__ out,
                          int L)
{
    const int b = blockIdx.x;
    const unsigned* __restrict__ k  = keys + (size_t)b * L;
    const float*    __restrict__ xb = x    + (size_t)b * L * DFEAT;
    const unsigned* __restrict__ h  = hist + (size_t)b * HBINS;

    __shared__ unsigned s_h[HBINS];        // 16 KB
    __shared__ unsigned s_w[32];
    __shared__ unsigned cnt[256];
    __shared__ int      selIdx[TOPK];      // 4 KB
    __shared__ unsigned candKey[CAND_CAP]; // 8 KB
    __shared__ int      candIdx[CAND_CAP]; // 8 KB
    __shared__ int      eqIdx[EQ_CAP];     // 4 KB
    __shared__ float    red[32][33];       // 4.2 KB
    __shared__ int      s_D, s_nsel, s_ncand, s_neq;
    __shared__ unsigned s_kk, s_tkey, s_kk2;

    const int tid  = threadIdx.x;
    const int lane = tid & 31;
    const int wid  = tid >> 5;

    if (tid == 0) { s_nsel = 0; s_ncand = 0; s_neq = 0; }
#pragma unroll
    for (int j = 0; j < 4; j++) s_h[tid + j * 1024] = h[tid + j * 1024];
    __syncthreads();

    // ---- suffix scan over histogram: bin D + in-bin rank kk ----
    {
        const unsigned t4 = s_h[tid * 4] + s_h[tid * 4 + 1]
                          + s_h[tid * 4 + 2] + s_h[tid * 4 + 3];
        unsigned v = t4;
#pragma unroll
        for (int off = 1; off < 32; off <<= 1) {
            unsigned o = __shfl_down_sync(0xffffffffu, v, off);
            if (lane + off < 32) v += o;
        }
        if (lane == 0) s_w[wid] = v;
        __syncthreads();
        if (wid == 0) {
            const unsigned tv = s_w[lane];
            unsigned iv = tv;
#pragma unroll
            for (int off = 1; off < 32; off <<= 1) {
                unsigned o = __shfl_down_sync(0xffffffffu, iv, off);
                if (lane + off < 32) iv += o;
            }
            s_w[lane] = iv - tv;
        }
        __syncthreads();

        const long long E = (long long)s_w[wid] + (long long)(v - t4);
        long long r = (long long)TOPK - E;
        if (r >= 1 && r <= (long long)t4) {
            for (int d = tid * 4 + 3; d >= tid * 4; d--) {
                const unsigned c = s_h[d];
                if (r <= (long long)c) { s_D = d; s_kk = (unsigned)r; break; }
                r -= (long long)c;
            }
        }
        __syncthreads();
    }

    const int D = s_D;
    const unsigned kk = s_kk;
    const unsigned hiD = (unsigned)D << 20;

    // ---- single key pass: compact winners (>D), stash bin-D candidates ----
    const int nvec = L >> 2;
    const int tail = nvec << 2;
    const int nvecR = (nvec + 1023) & ~1023;           // warp-uniform trip count

    for (int i = tid; i < nvecR; i += 1024) {
        const bool valid = (i < nvec);
        uint4 kv = make_uint4(0u, 0u, 0u, 0u);
        if (valid) kv = __ldg((const uint4*)k + i);
        const int base = i << 2;
        const unsigned ks[4] = {kv.x, kv.y, kv.z, kv.w};
#pragma unroll
        for (int c = 0; c < 4; c++) {
            const int top = (int)(ks[c] >> 20);
            const bool win  = valid && (top >  D);
            const bool cand = valid && (top == D);
            unsigned m;
            const int pw = warp_offset(win,  &s_nsel,  lane, m);
            if (win  && pw < TOPK)     selIdx[pw] = base + c;
            const int pc = warp_offset(cand, &s_ncand, lane, m);
            if (cand && pc < CAND_CAP) { candKey[pc] = ks[c]; candIdx[pc] = base + c; }
        }
    }
    for (int i = tail + tid; i < L; i += 1024) {       // generic tail (empty here)
        const unsigned key = __ldg(k + i);
        const int top = (int)(key >> 20);
        if (top > D) {
            const int p = atomicAdd(&s_nsel, 1);
            if (p < TOPK) selIdx[p] = i;
        } else if (top == D) {
            const int p = atomicAdd(&s_ncand, 1);
            if (p < CAND_CAP) { candKey[p] = key; candIdx[p] = i; }
        }
    }
    __syncthreads();
    const int nc = s_ncand;
    if (tid == 0) { s_tkey = hiD; s_kk2 = kk; }
    __syncthreads();

    // ---- refine low 20 bits of the threshold ----
    const int shifts[3] = {12, 4, 0};
    const int widths[3] = {8, 8, 4};

    if (nc <= CAND_CAP) {
        for (int p = 0; p < 3; p++) {
            const int sh = shifts[p], wd = widths[p];
            const unsigned maskAbove = ~((1u << (sh + wd)) - 1u);
            const unsigned bins = 1u << wd;
            if (tid < 256) cnt[tid] = 0u;
            __syncthreads();
            const unsigned pref = s_tkey;
            for (int j = tid; j < nc; j += 1024) {
                const unsigned key = candKey[j];
                if ((key & maskAbove) == pref)
                    atomicAdd(&cnt[(key >> sh) & (bins - 1u)], 1u);
            }
            __syncthreads();
            if (tid == 0) {
                unsigned kk2 = s_kk2;
                for (int d = (int)bins - 1; d >= 0; d--) {
                    const unsigned c = cnt[d];
                    if (kk2 <= c) { s_tkey = pref | ((unsigned)d << sh); break; }
                    kk2 -= c;
                }
                s_kk2 = kk2;
            }
            __syncthreads();
        }
        const unsigned t = s_tkey;
        for (int j = tid; j < nc; j += 1024) {
            const unsigned key = candKey[j];
            if (key > t) {
                const int p = atomicAdd(&s_nsel, 1);
                if (p < TOPK) selIdx[p] = candIdx[j];
            } else if (key == t) {
                const int p = atomicAdd(&s_neq, 1);
                if (p < EQ_CAP) eqIdx[p] = candIdx[j];
            }
        }
    } else {
        // fallback: radix + compaction over gmem keys (pathological bin)
        for (int p = 0; p < 3; p++) {
            const int sh = shifts[p], wd = widths[p];
            const unsigned maskAbove = ~((1u << (sh + wd)) - 1u);
            const unsigned bins = 1u << wd;
            if (tid < 256) cnt[tid] = 0u;
            __syncthreads();
            const unsigned pref = s_tkey;
            for (int i = tid; i < L; i += 1024) {
                const unsigned key = __ldg(k + i);
                if ((key & maskAbove) == pref)
                    atomicAdd(&cnt[(key >> sh) & (bins - 1u)], 1u);
            }
            __syncthreads();
            if (tid == 0) {
                unsigned kk2 = s_kk2;
                for (int d = (int)bins - 1; d >= 0; d--) {
                    const unsigned c = cnt[d];
                    if (kk2 <= c) { s_tkey = pref | ((unsigned)d << sh); break; }
                    kk2 -= c;
                }
                s_kk2 = kk2;
            }
            __syncthreads();
        }
        const unsigned t = s_tkey;
        for (int i = tid; i < L; i += 1024) {
            const unsigned key = __ldg(k + i);
            if ((key & 0xFFF00000u) != hiD) continue;
            if (key > t) {
                const int p = atomicAdd(&s_nsel, 1);
                if (p < TOPK) selIdx[p] = i;
            } else if (key == t) {
                const int p = atomicAdd(&s_neq, 1);
                if (p < EQ_CAP) eqIdx[p] = i;
            }
        }
    }
    __syncthreads();

    // ---- ties: take kk_t smallest indices (jax top_k tie-break) ----
    if (tid == 0) {
        int kk_t = (int)s_kk2;
        const int neq = (s_neq < EQ_CAP) ? s_neq : EQ_CAP;
        if (kk_t > neq) kk_t = neq;
        const int base = s_nsel;
        for (int j = 0; j < kk_t; j++) {
            int mi = j;
            for (int m = j + 1; m < neq; m++)
                if (eqIdx[m] < eqIdx[mi]) mi = m;
            const int tmp = eqIdx[j]; eqIdx[j] = eqIdx[mi]; eqIdx[mi] = tmp;
            if (base + j < TOPK) selIdx[base + j] = eqIdx[j];
        }
        const int total = base + kk_t;
        s_nsel = (total < TOPK) ? total : TOPK;
    }
    __syncthreads();

    // ---- gather-sum: warp w handles points [w*32, (w+1)*32), 4-way MLP ----
    const int n = s_nsel;
    const int jbeg = wid * 32;
    const int jend = min(n, jbeg + 32);
    float a0 = 0.f, a1 = 0.f, a2 = 0.f, a3 = 0.f;
    int j = jbeg;
    for (; j + 3 < jend; j += 4) {
        const int i0 = selIdx[j + 0];
        const int i1 = selIdx[j + 1];
        const int i2 = selIdx[j + 2];
        const int i3 = selIdx[j + 3];
        a0 += __ldg(xb + (size_t)i0 * DFEAT + lane);
        a1 += __ldg(xb + (size_t)i1 * DFEAT + lane);
        a2 += __ldg(xb + (size_t)i2 * DFEAT + lane);
        a3 += __ldg(xb + (size_t)i3 * DFEAT + lane);
    }
    for (; j < jend; j++)
        a0 += __ldg(xb + (size_t)selIdx[j] * DFEAT + lane);
    red[wid][lane] = (a0 + a1) + (a2 + a3);
    __syncthreads();

    if (wid == 0) {
        float v = 0.f;
#pragma unroll
        for (int ww = 0; ww < 32; ww++) v += red[ww][lane];
        v /= (float)L;
        float ss = v * v;
#pragma unroll
        for (int o = 16; o; o >>= 1) ss += __shfl_xor_sync(0xffffffffu, ss, o);
        const float norm = sqrtf(ss);
        out[b * DFEAT + lane] = v / fmaxf(norm, 1e-12f);
    }
}

extern "C" void kernel_launch(void* const* d_in, const int* in_sizes, int n_in,
                              void* d_out, int out_size)
{
    const float* x  = (const float*)d_in[0];   // [B*L, 32] fp32
    const float* w  = (const float*)d_in[2];   // [32]
    const float* bb = (const float*)d_in[3];   // [1]
    float* out = (float*)d_out;                // [B, 32]

    const int B = in_sizes[1];
    const int L = in_sizes[0] / (B * DFEAT);
    const int npts = B * L;

    unsigned *keys = nullptr, *hist = nullptr;
    cudaGetSymbolAddress((void**)&keys, g_keys);
    cudaGetSymbolAddress((void**)&hist, g_hist);

    cudaMemsetAsync(hist, 0, (size_t)B * HBINS * sizeof(unsigned));

    {
        const int threads = 256;
        const long long total = (long long)npts * 4;
        const int grid = (int)((total + threads - 1) / threads);
        score_kernel<<<grid, threads>>>(x, w, bb, keys, hist, npts, L);
    }
    select_reduce_kernel<<<B, 1024>>>(x, keys, hist, out, L);
}

// round 7
// speedup vs baseline: 2.1372x; 2.1372x over previous
#include <cuda_runtime.h>
#include <math.h>

#define TOPK     1024
#define DFEAT    32
#define HBINS    4096          // top-12-bit histogram
#define CAND_CAP 2048
#define EQ_CAP   1024

__device__ unsigned g_keys[4000000];

// ---------------------------------------------------------------------------
// Kernel 1 (R1 form, measured ~82us): 8 threads/point, coalesced float4,
// no atomics anywhere.
// ---------------------------------------------------------------------------
__global__ void score_kernel(const float* __restrict__ x,
                             const float* __restrict__ w,
                             const float* __restrict__ b,
                             unsigned* __restrict__ keys,
                             int npts)
{
    const int t = blockIdx.x * blockDim.x + threadIdx.x;
    const int point = t >> 3;
    const int lane8 = t & 7;
    if (point >= npts) return;

    const float4 xv = __ldg((const float4*)(x + (size_t)point * DFEAT) + lane8);
    const float4 wv = __ldg((const float4*)w + lane8);

    float s = xv.x * wv.x + xv.y * wv.y + xv.z * wv.z + xv.w * wv.w;
    s += __shfl_xor_sync(0xffffffffu, s, 1);
    s += __shfl_xor_sync(0xffffffffu, s, 2);
    s += __shfl_xor_sync(0xffffffffu, s, 4);

    if (lane8 == 0) {
        s += __ldg(b);
        unsigned u = __float_as_uint(s);
        u = (u & 0x80000000u) ? ~u : (u | 0x80000000u);   // monotone transform
        keys[point] = u;
    }
}

// ---------------------------------------------------------------------------
// Kernel 2: one block per segment.
//   pass A: vectorized smem histogram (top 12 bits)       (~3-4us measured)
//   suffix scan -> bin D + in-bin rank kk                 (cheap)
//   pass B: vectorized compact, RARE-BRANCH form: 1 setp per element,
//           plain smem atomics only for the ~3% that pass (key >= D<<20)
//   tiny smem radix on bin-D candidates -> exact threshold + tie count
//   4-way-MLP warp-per-point gather-sum, /L, L2 normalize
// ---------------------------------------------------------------------------
__global__ __launch_bounds__(1024, 1)
void select_reduce_kernel(const float* __restrict__ x,
                          const unsigned* __restrict__ keys,
                          float* __restrict__ out,
                          int L)
{
    const int b = blockIdx.x;
    const unsigned* __restrict__ k  = keys + (size_t)b * L;
    const float*    __restrict__ xb = x    + (size_t)b * L * DFEAT;

    __shared__ unsigned s_h[HBINS];        // 16 KB
    __shared__ unsigned s_w[32];
    __shared__ unsigned cnt[256];
    __shared__ int      selIdx[TOPK];      // 4 KB
    __shared__ unsigned candKey[CAND_CAP]; // 8 KB
    __shared__ int      candIdx[CAND_CAP]; // 8 KB
    __shared__ int      eqIdx[EQ_CAP];     // 4 KB
    __shared__ float    red[32][33];       // 4.2 KB
    __shared__ int      s_D, s_nsel, s_ncand, s_neq;
    __shared__ unsigned s_kk, s_tkey, s_kk2;

    const int tid  = threadIdx.x;
    const int lane = tid & 31;
    const int wid  = tid >> 5;

    if (tid == 0) { s_nsel = 0; s_ncand = 0; s_neq = 0; }
#pragma unroll
    for (int j = 0; j < 4; j++) s_h[tid + j * 1024] = 0u;
    __syncthreads();

    const int nvec = L >> 2;               // uint4 chunks
    const int tail = nvec << 2;

    // ---- pass A: histogram of top 12 bits ----
    for (int i = tid; i < nvec; i += 1024) {
        const uint4 kv = __ldg((const uint4*)k + i);
        atomicAdd(&s_h[kv.x >> 20], 1u);
        atomicAdd(&s_h[kv.y >> 20], 1u);
        atomicAdd(&s_h[kv.z >> 20], 1u);
        atomicAdd(&s_h[kv.w >> 20], 1u);
    }
    for (int i = tail + tid; i < L; i += 1024)
        atomicAdd(&s_h[__ldg(k + i) >> 20], 1u);
    __syncthreads();

    // ---- suffix scan: find bin D and in-bin rank kk ----
    {
        const unsigned t4 = s_h[tid * 4] + s_h[tid * 4 + 1]
                          + s_h[tid * 4 + 2] + s_h[tid * 4 + 3];
        unsigned v = t4;
#pragma unroll
        for (int off = 1; off < 32; off <<= 1) {
            unsigned o = __shfl_down_sync(0xffffffffu, v, off);
            if (lane + off < 32) v += o;
        }
        if (lane == 0) s_w[wid] = v;
        __syncthreads();
        if (wid == 0) {
            const unsigned tv = s_w[lane];
            unsigned iv = tv;
#pragma unroll
            for (int off = 1; off < 32; off <<= 1) {
                unsigned o = __shfl_down_sync(0xffffffffu, iv, off);
                if (lane + off < 32) iv += o;
            }
            s_w[lane] = iv - tv;
        }
        __syncthreads();

        const long long E = (long long)s_w[wid] + (long long)(v - t4);
        long long r = (long long)TOPK - E;
        if (r >= 1 && r <= (long long)t4) {
            for (int d = tid * 4 + 3; d >= tid * 4; d--) {
                const unsigned c = s_h[d];
                if (r <= (long long)c) { s_D = d; s_kk = (unsigned)r; break; }
                r -= (long long)c;
            }
        }
        __syncthreads();
    }

    const int D = s_D;
    const unsigned kk = s_kk;
    const unsigned hiD  = (unsigned)D << 20;        // bin-D lower bound
    const unsigned hiD1 = hiD + (1u << 20);         // bin-D upper bound (exclusive)

    // ---- pass B: rare-branch compact (predicate fires ~3% of elements) ----
    for (int i = tid; i < nvec; i += 1024) {
        const uint4 kv = __ldg((const uint4*)k + i);
        const int base = i << 2;
        const unsigned ks[4] = {kv.x, kv.y, kv.z, kv.w};
#pragma unroll
        for (int c = 0; c < 4; c++) {
            const unsigned key = ks[c];
            if (key >= hiD) {                        // RARE
                if (key >= hiD1) {                   // definite winner
                    const int p = atomicAdd(&s_nsel, 1);
                    if (p < TOPK) selIdx[p] = base + c;
                } else {                             // bin-D candidate
                    const int p = atomicAdd(&s_ncand, 1);
                    if (p < CAND_CAP) { candKey[p] = key; candIdx[p] = base + c; }
                }
            }
        }
    }
    for (int i = tail + tid; i < L; i += 1024) {
        const unsigned key = __ldg(k + i);
        if (key >= hiD) {
            if (key >= hiD1) {
                const int p = atomicAdd(&s_nsel, 1);
                if (p < TOPK) selIdx[p] = i;
            } else {
                const int p = atomicAdd(&s_ncand, 1);
                if (p < CAND_CAP) { candKey[p] = key; candIdx[p] = i; }
            }
        }
    }
    __syncthreads();
    const int nc = s_ncand;
    if (tid == 0) { s_tkey = hiD; s_kk2 = kk; }
    __syncthreads();

    // ---- refine low 20 bits of the threshold ----
    const int shifts[3] = {12, 4, 0};
    const int widths[3] = {8, 8, 4};

    if (nc <= CAND_CAP) {
        for (int p = 0; p < 3; p++) {
            const int sh = shifts[p], wd = widths[p];
            const unsigned maskAbove = ~((1u << (sh + wd)) - 1u);
            const unsigned bins = 1u << wd;
            if (tid < 256) cnt[tid] = 0u;
            __syncthreads();
            const unsigned pref = s_tkey;
            for (int j = tid; j < nc; j += 1024) {
                const unsigned key = candKey[j];
                if ((key & maskAbove) == pref)
                    atomicAdd(&cnt[(key >> sh) & (bins - 1u)], 1u);
            }
            __syncthreads();
            if (tid == 0) {
                unsigned kk2 = s_kk2;
                for (int d = (int)bins - 1; d >= 0; d--) {
                    const unsigned c = cnt[d];
                    if (kk2 <= c) { s_tkey = pref | ((unsigned)d << sh); break; }
                    kk2 -= c;
                }
                s_kk2 = kk2;
            }
            __syncthreads();
        }
        const unsigned t = s_tkey;
        for (int j = tid; j < nc; j += 1024) {
            const unsigned key = candKey[j];
            if (key > t) {
                const int p = atomicAdd(&s_nsel, 1);
                if (p < TOPK) selIdx[p] = candIdx[j];
            } else if (key == t) {
                const int p = atomicAdd(&s_neq, 1);
                if (p < EQ_CAP) eqIdx[p] = candIdx[j];
            }
        }
    } else {
        // fallback: radix + compaction over gmem keys (pathological bin)
        for (int p = 0; p < 3; p++) {
            const int sh = shifts[p], wd = widths[p];
            const unsigned maskAbove = ~((1u << (sh + wd)) - 1u);
            const unsigned bins = 1u << wd;
            if (tid < 256) cnt[tid] = 0u;
            __syncthreads();
            const unsigned pref = s_tkey;
            for (int i = tid; i < L; i += 1024) {
                const unsigned key = __ldg(k + i);
                if ((key & maskAbove) == pref)
                    atomicAdd(&cnt[(key >> sh) & (bins - 1u)], 1u);
            }
            __syncthreads();
            if (tid == 0) {
                unsigned kk2 = s_kk2;
                for (int d = (int)bins - 1; d >= 0; d--) {
                    const unsigned c = cnt[d];
                    if (kk2 <= c) { s_tkey = pref | ((unsigned)d << sh); break; }
                    kk2 -= c;
                }
                s_kk2 = kk2;
            }
            __syncthreads();
        }
        const unsigned t = s_tkey;
        for (int i = tid; i < L; i += 1024) {
            const unsigned key = __ldg(k + i);
            if (key < hiD || key >= hiD1) continue;
            if (key > t) {
                const int p = atomicAdd(&s_nsel, 1);
                if (p < TOPK) selIdx[p] = i;
            } else if (key == t) {
                const int p = atomicAdd(&s_neq, 1);
                if (p < EQ_CAP) eqIdx[p] = i;
            }
        }
    }
    __syncthreads();

    // ---- ties: take kk_t smallest indices (jax top_k tie-break) ----
    if (tid == 0) {
        int kk_t = (int)s_kk2;
        const int neq = (s_neq < EQ_CAP) ? s_neq : EQ_CAP;
        if (kk_t > neq) kk_t = neq;
        const int base = s_nsel;
        for (int j = 0; j < kk_t; j++) {
            int mi = j;
            for (int m = j + 1; m < neq; m++)
                if (eqIdx[m] < eqIdx[mi]) mi = m;
            const int tmp = eqIdx[j]; eqIdx[j] = eqIdx[mi]; eqIdx[mi] = tmp;
            if (base + j < TOPK) selIdx[base + j] = eqIdx[j];
        }
        const int total = base + kk_t;
        s_nsel = (total < TOPK) ? total : TOPK;
    }
    __syncthreads();

    // ---- gather-sum: warp w handles points [w*32, (w+1)*32), 4-way MLP ----
    const int n = s_nsel;
    const int jbeg = wid * 32;
    const int jend = min(n, jbeg + 32);
    float a0 = 0.f, a1 = 0.f, a2 = 0.f, a3 = 0.f;
    int j = jbeg;
    for (; j + 3 < jend; j += 4) {
        const int i0 = selIdx[j + 0];
        const int i1 = selIdx[j + 1];
        const int i2 = selIdx[j + 2];
        const int i3 = selIdx[j + 3];
        a0 += __ldg(xb + (size_t)i0 * DFEAT + lane);
        a1 += __ldg(xb + (size_t)i1 * DFEAT + lane);
        a2 += __ldg(xb + (size_t)i2 * DFEAT + lane);
        a3 += __ldg(xb + (size_t)i3 * DFEAT + lane);
    }
    for (; j < jend; j++)
        a0 += __ldg(xb + (size_t)selIdx[j] * DFEAT + lane);
    red[wid][lane] = (a0 + a1) + (a2 + a3);
    __syncthreads();

    if (wid == 0) {
        float v = 0.f;
#pragma unroll
        for (int ww = 0; ww < 32; ww++) v += red[ww][lane];
        v /= (float)L;
        float ss = v * v;
#pragma unroll
        for (int o = 16; o; o >>= 1) ss += __shfl_xor_sync(0xffffffffu, ss, o);
        const float norm = sqrtf(ss);
        out[b * DFEAT + lane] = v / fmaxf(norm, 1e-12f);
    }
}

extern "C" void kernel_launch(void* const* d_in, const int* in_sizes, int n_in,
                              void* d_out, int out_size)
{
    const float* x  = (const float*)d_in[0];   // [B*L, 32] fp32
    const float* w  = (const float*)d_in[2];   // [32]
    const float* bb = (const float*)d_in[3];   // [1]
    float* out = (float*)d_out;                // [B, 32]

    const int B = in_sizes[1];
    const int L = in_sizes[0] / (B * DFEAT);
    const int npts = B * L;

    unsigned* keys = nullptr;
    cudaGetSymbolAddress((void**)&keys, g_keys);

    {
        const int threads = 256;
        const long long total = (long long)npts * 8;
        const int grid = (int)((total + threads - 1) / threads);
        score_kernel<<<grid, threads>>>(x, w, bb, keys, npts);
    }
    select_reduce_kernel<<<B, 1024>>>(x, keys, out, L);
}